// round 13
// baseline (speedup 1.0000x reference)
#include <cuda_runtime.h>
#include <math.h>

#define VV     50257
#define NT     256
#define NB     512                    // histogram bins over [BLO, T0]
#define SCAP   512                    // winner buffer == sort size
#define TOPK   100
#define T0     2.5f                   // winners kept exactly above this
#define BLO    -6.5f
#define BDD    0.017578125f           // (T0-BLO)/NB = 9/512
#define BINV   56.88888888888889f     // NB/(T0-BLO)
#define S1SC   16384.0f               // residual quantizer (units of BDD/16384)
#define S1DQ   (0.017578125f/16384.0f)
#define MASK40 ((1ULL<<40)-1ULL)
#define LOG2E  1.44269504088896340736f
#define LN2    0.69314718055994530942f

// 2^y via round-to-int bit trick + degree-5 poly; FMA/ALU only, no MUFU.
__device__ __forceinline__ float exp2_fast(float y) {
    y = fmaxf(y, -120.0f);
    float r = y + 12582912.0f;
    int   n = __float_as_int(r) - 0x4B400000;
    float f = y - (r - 12582912.0f);
    float p = 1.3333558146428443e-3f;
    p = fmaf(p, f, 9.6181291076284772e-3f);
    p = fmaf(p, f, 5.5504108664821580e-2f);
    p = fmaf(p, f, 2.4022650695910071e-1f);
    p = fmaf(p, f, 6.9314718055994531e-1f);
    p = fmaf(p, f, 1.0f);
    return __uint_as_float(__float_as_uint(p) + ((unsigned)n << 23));
}

__device__ __forceinline__ float blockMaxF(float v, float* red, int tid) {
    int lane = tid & 31, w = tid >> 5;
    #pragma unroll
    for (int k = 16; k; k >>= 1) v = fmaxf(v, __shfl_xor_sync(~0u, v, k));
    if (lane == 0) red[w] = v;
    __syncthreads();
    if (tid < 32) {
        float m = (tid < 8) ? red[tid] : -INFINITY;
        #pragma unroll
        for (int k = 4; k; k >>= 1) m = fmaxf(m, __shfl_xor_sync(~0u, m, k));
        if (tid == 0) red[0] = m;
    }
    __syncthreads();
    float r = red[0]; __syncthreads();
    return r;
}
__device__ __forceinline__ int blockSumI(int v, int* redi, int tid) {
    int lane = tid & 31, w = tid >> 5;
    #pragma unroll
    for (int k = 16; k; k >>= 1) v += __shfl_xor_sync(~0u, v, k);
    if (lane == 0) redi[w] = v;
    __syncthreads();
    if (tid < 32) {
        int s = (tid < 8) ? redi[tid] : 0;
        #pragma unroll
        for (int k = 4; k; k >>= 1) s += __shfl_xor_sync(~0u, s, k);
        if (tid == 0) redi[0] = s;
    }
    __syncthreads();
    int r = redi[0]; __syncthreads();
    return r;
}
__device__ __forceinline__ int cgtGlobal(const float* __restrict__ x, float t,
                                         int tid, int* redi) {
    int c = 0;
    #pragma unroll 8
    for (int i = tid; i < VV; i += NT) c += (__ldg(x + i) > t);
    return blockSumI(c, redi, tid);
}

__global__ void __launch_bounds__(NT)
pts_all(const float* __restrict__ inp, const int* __restrict__ tokens,
        const float* __restrict__ W1, const float* __restrict__ b1,
        const float* __restrict__ W2, const float* __restrict__ b2,
        const float* __restrict__ W3, const float* __restrict__ b3,
        float* __restrict__ out)
{
    __shared__ unsigned long long hP[NB];   // packed: count<<40 | biased S1 units
    __shared__ float buf[SCAP];
    __shared__ int   scnt;
    __shared__ float redf[8];
    __shared__ int   redi[8];
    __shared__ float sh1[5];
    __shared__ float sAB[2];

    const int tid  = threadIdx.x;
    const int lane = tid & 31;
    const int wid  = tid >> 5;
    const int row  = blockIdx.x;
    const float* x = inp + (size_t)row * VV;

    for (int i = tid; i < NB; i += NT) hP[i] = 0ULL;
    if (tid == 0) scnt = 0;
    __syncthreads();

    // ---- one streaming pass: moment histogram (<=T0) + exact winners (>T0) ----
    int lowc = 0;                               // elements below BLO -> forces exact path
    #define HIST1(xv) do {                                                          \
        if ((xv) <= T0) {                                                           \
            lowc += ((xv) < BLO);                                                   \
            float g  = fmaf(fmaxf((xv), BLO), BINV, -BLO * BINV);                   \
            int   bi = min((int)g, NB - 1);                                         \
            float eu = g - ((float)bi + 0.5f);   /* in [-0.5, 0.5] */               \
            unsigned e1 = (unsigned)__float2int_rn(fmaf(eu, S1SC, 8192.0f));        \
            atomicAdd(&hP[bi], (1ULL << 40) | (unsigned long long)e1);              \
        } else {                                                                    \
            int p = atomicAdd(&scnt, 1);                                            \
            if (p < SCAP) buf[p] = (xv);                                            \
        }                                                                           \
    } while (0)

    const int nb = VV / (8 * NT);               // 24 full batches
    #pragma unroll 1
    for (int k = 0; k < nb; k++) {
        const int ib = k * (8 * NT) + tid;
        float v[8];
        #pragma unroll
        for (int j = 0; j < 8; j++) v[j] = __ldg(x + ib + j * NT);
        #pragma unroll
        for (int j = 0; j < 8; j++) HIST1(v[j]);
    }
    for (int i = nb * (8 * NT) + tid; i < VV; i += NT) {
        float v = __ldg(x + i);
        HIST1(v);
    }
    #undef HIST1

    __syncthreads();
    int cnt  = scnt;
    int nlow = blockSumI(lowc, redi, tid);
    const int bad = (cnt > SCAP) || (cnt < TOPK) || (nlow > 0);
    float M, tSel = T0;
    int bc;

    if (!bad) {
        bc = cnt;                               // all winners exact, 100..512
    } else {
        // ---- exact fallback: max scan + bisect threshold + exact gather ----
        float mx = -INFINITY;
        #pragma unroll 8
        for (int i = tid; i < VV; i += NT) mx = fmaxf(mx, __ldg(x + i));
        M = blockMaxF(mx, redf, tid);
        float gap = 8.0f, lo = M - gap, hi = M;
        int c = cgtGlobal(x, lo, tid, redi);
        for (int e = 0; e < 12 && c < TOPK; e++) {
            gap *= 4.0f; lo = M - gap;
            c = cgtGlobal(x, lo, tid, redi);
        }
        float ts = hi; int found = 0;
        if (c >= TOPK && c <= SCAP) { ts = lo; found = 1; }
        for (int it = 0; it < 50 && !found; it++) {
            float mid = 0.5f * (lo + hi);
            if (mid <= lo || mid >= hi) break;  // tie plateau -> hi
            c = cgtGlobal(x, mid, tid, redi);
            if (c >= TOPK && c <= SCAP) { ts = mid; found = 1; }
            else if (c > SCAP) lo = mid; else hi = mid;
        }
        tSel = ts;
        __syncthreads();
        if (tid == 0) scnt = 0;
        __syncthreads();
        #pragma unroll 4
        for (int i = tid; i < VV; i += NT) {
            float v = __ldg(x + i);
            if (v > tSel) { int p = atomicAdd(&scnt, 1); if (p < SCAP) buf[p] = v; }
        }
        __syncthreads();
        bc = min(scnt, SCAP);
    }

    for (int i = tid; i < SCAP; i += NT) if (i >= bc) buf[i] = -INFINITY;
    __syncthreads();

    // ---- bitonic sort 512 descending (2 elems/thread); launders push order ----
    #pragma unroll 1
    for (int k = 2; k <= SCAP; k <<= 1) {
        #pragma unroll 1
        for (int j = k >> 1; j > 0; j >>= 1) {
            #pragma unroll
            for (int mb = 0; mb < SCAP; mb += NT) {
                int i = mb + tid, ixj = i ^ j;
                if (ixj > i) {
                    float va = buf[i], vb = buf[ixj];
                    bool desc = ((i & k) == 0);
                    if (desc ? (va < vb) : (va > vb)) { buf[i] = vb; buf[ixj] = va; }
                }
            }
            __syncthreads();
        }
    }
    if (tid < TOPK && tid >= bc) buf[tid] = tSel;   // tie-plateau fill (bad path)
    __syncthreads();
    if (!bad) M = buf[0];                           // row max is the largest winner

    // ---- tiny MLP -> temperature -> (a, b) ----
    if (wid < 5) {
        float acc = 0.0f;
        #pragma unroll
        for (int i = lane; i < TOPK; i += 32)
            acc = fmaf(__ldg(W1 + wid * TOPK + i), buf[i], acc);
        #pragma unroll
        for (int k = 16; k; k >>= 1) acc += __shfl_xor_sync(~0u, acc, k);
        if (lane == 0) sh1[wid] = fmaxf(acc + __ldg(b1 + wid), 0.0f);
    }
    __syncthreads();
    if (tid == 0) {
        float h2[5];
        #pragma unroll
        for (int j = 0; j < 5; ++j) {
            float a2 = __ldg(b2 + j);
            #pragma unroll
            for (int i = 0; i < 5; ++i) a2 = fmaf(__ldg(W2 + j * 5 + i), sh1[i], a2);
            h2[j] = fmaxf(a2, 0.0f);
        }
        float t0 = __ldg(b3);
        #pragma unroll
        for (int i = 0; i < 5; ++i) t0 = fmaf(__ldg(W3 + i), h2[i], t0);
        t0 = fabsf(t0);
        float sp   = (t0 > 20.0f) ? t0 : log1pf(expf(t0));   // >= ln2 by construction
        float temp = fmaxf(sp, 1e-5f);
        float a    = LOG2E / temp;
        sAB[0] = a;
        sAB[1] = -M * a;
    }
    __syncthreads();
    const float a  = sAB[0];
    const float bb = sAB[1];

    // ---- softmax denominator ----
    float s = 0.0f;
    if (!bad) {
        const float invT = a * LN2;                 // 1/temp
        #pragma unroll
        for (int q = 0; q < 2; q++) {
            int b = tid + q * NT;
            unsigned long long p = hP[b];
            int       n   = (int)(p >> 40);
            long long s1b = (long long)(p & MASK40);
            float S1 = (float)(s1b - (long long)n * 8192) * S1DQ;   // sum of (x - c_b)
            float cb = fmaf((float)b + 0.5f, BDD, BLO);
            s += exp2_fast(fmaf(cb, a, bb)) * ((float)n + S1 * invT);
            s += exp2_fast(fmaf(buf[b], a, bb));    // exact winners; -INF pads ~ 0
        }
    } else {
        #pragma unroll 4
        for (int i = tid; i < VV; i += NT)          // exact sum, fixed per-thread order
            s += exp2_fast(fmaf(__ldg(x + i), a, bb));
    }
    #pragma unroll
    for (int k = 16; k; k >>= 1) s += __shfl_xor_sync(~0u, s, k);
    if (lane == 0) redf[wid] = s;
    __syncthreads();
    if (tid == 0) {
        float tot = 0.0f;
        #pragma unroll
        for (int k = 0; k < 8; k++) tot += redf[k]; // fixed order: deterministic
        int tok = tokens[row];
        tok = (tok < 0) ? 0 : ((tok >= VV) ? VV - 1 : tok);
        out[row] = exp2_fast(fmaf(__ldg(x + tok), a, bb)) / tot;
    }
}

extern "C" void kernel_launch(void* const* d_in, const int* in_sizes, int n_in,
                              void* d_out, int out_size)
{
    const float* inp    = (const float*)d_in[0];
    const int*   tokens = (const int*)d_in[1];
    const float* W1     = (const float*)d_in[2];
    const float* b1     = (const float*)d_in[3];
    const float* W2     = (const float*)d_in[4];
    const float* b2     = (const float*)d_in[5];
    const float* W3     = (const float*)d_in[6];
    const float* b3     = (const float*)d_in[7];
    float*       o      = (float*)d_out;

    const int N = in_sizes[1];
    pts_all<<<N, NT>>>(inp, tokens, W1, b1, W2, b2, W3, b3, o);
}

// round 14
// speedup vs baseline: 2.5528x; 2.5528x over previous
#include <cuda_runtime.h>
#include <math.h>

#define VV      50257
#define NT      256
#define NSLOT   8                    // per-thread winner slots (+1 trash)
#define SCAP    512                  // per-CTA smem winner staging
#define WCAPG   2048                 // global per-row winner cap
#define FCAP    256                  // finalist buffer
#define TOPK    100
#define THR0    2.5f                 // static gather threshold; certificate+fallback cover any data
#define SEG     4
#define SEGLEN  12565
#define MAXN    8192

__device__ float    g_a[MAXN];
__device__ float    g_b[MAXN];
__device__ float    g_part[MAXN * SEG];
__device__ unsigned g_cnt[MAXN];     // zero-init; K1b resets for next graph replay
__device__ float    g_win[(size_t)MAXN * WCAPG];

// 2^y via round-to-int bit trick + degree-5 poly; FMA/ALU only, no MUFU.
__device__ __forceinline__ float exp2_fast(float y) {
    y = fmaxf(y, -120.0f);
    float r = y + 12582912.0f;
    int   n = __float_as_int(r) - 0x4B400000;
    float f = y - (r - 12582912.0f);
    float p = 1.3333558146428443e-3f;
    p = fmaf(p, f, 9.6181291076284772e-3f);
    p = fmaf(p, f, 5.5504108664821580e-2f);
    p = fmaf(p, f, 2.4022650695910071e-1f);
    p = fmaf(p, f, 6.9314718055994531e-1f);
    p = fmaf(p, f, 1.0f);
    return __uint_as_float(__float_as_uint(p) + ((unsigned)n << 23));
}

// ---------------- block reductions (8 warps, 256 threads) ----------------
__device__ __forceinline__ float blockMaxF(float v, float* red, int tid) {
    int lane = tid & 31, w = tid >> 5;
    #pragma unroll
    for (int k = 16; k; k >>= 1) v = fmaxf(v, __shfl_xor_sync(~0u, v, k));
    if (lane == 0) red[w] = v;
    __syncthreads();
    if (tid < 32) {
        float m = (tid < 8) ? red[tid] : -INFINITY;
        #pragma unroll
        for (int k = 4; k; k >>= 1) m = fmaxf(m, __shfl_xor_sync(~0u, m, k));
        if (tid == 0) red[0] = m;
    }
    __syncthreads();
    float r = red[0]; __syncthreads();
    return r;
}
__device__ __forceinline__ int blockSumI(int v, int* redi, int tid) {
    int lane = tid & 31, w = tid >> 5;
    #pragma unroll
    for (int k = 16; k; k >>= 1) v += __shfl_xor_sync(~0u, v, k);
    if (lane == 0) redi[w] = v;
    __syncthreads();
    if (tid < 32) {
        int s = (tid < 8) ? redi[tid] : 0;
        #pragma unroll
        for (int k = 4; k; k >>= 1) s += __shfl_xor_sync(~0u, s, k);
        if (tid == 0) redi[0] = s;
    }
    __syncthreads();
    int r = redi[0]; __syncthreads();
    return r;
}

// full-row count of (> t) from global (fallback only)
__device__ __forceinline__ int cgtGlobal(const float* __restrict__ x, float t,
                                         int tid, int* redi) {
    int c = 0;
    #pragma unroll 8
    for (int i = tid; i < VV; i += NT) c += (__ldg(x + i) > t);
    return blockSumI(c, redi, tid);
}

// =================== K1: branchless slot-store stream-gather ===================
__global__ void __launch_bounds__(NT)
k1_gather(const float* __restrict__ inp)
{
    __shared__ float    slots[(NSLOT + 1) * NT];  // per-thread columns; last row = trash
    __shared__ float    swin[SCAP];
    __shared__ int      scnt;
    __shared__ unsigned sbase;

    const int row = blockIdx.x >> 2;
    const int seg = blockIdx.x & 3;
    const int tid = threadIdx.x;
    const float* x = inp + (size_t)row * VV;
    const float t = THR0;
    const int s0 = seg * SEGLEN;
    const int s1 = min(VV, s0 + SEGLEN);

    if (tid == 0) scnt = 0;
    __syncthreads();

    // ---- hot stream: ZERO control flow (FSETP+SELP+STS+IADD per element) ----
    int c = 0;
    #define PROC1(v) do {                                        \
        bool p   = (v) > t;                                      \
        int  idx = p ? min(c, NSLOT - 1) : NSLOT;                \
        slots[idx * NT + tid] = (v);                             \
        c += (int)p;                                             \
    } while (0)

    const int nb = (s1 - s0) / (8 * NT);          // full 8-deep batches (6 per segment)
    #pragma unroll 1
    for (int k = 0; k < nb; k++) {
        const int ib = s0 + k * (8 * NT) + tid;
        float v[8];
        #pragma unroll
        for (int j = 0; j < 8; j++) v[j] = __ldg(x + ib + j * NT);
        #pragma unroll
        for (int j = 0; j < 8; j++) PROC1(v[j]);
    }
    for (int i = s0 + nb * (8 * NT) + tid; i < s1; i += NT) {    // tail (~277 elems/seg)
        float v = __ldg(x + i);
        PROC1(v);
    }
    #undef PROC1

    // ---- drain per-thread slots to staging (outside hot loop; ~0.3 iters avg) ----
    int cc = min(c, NSLOT);
    for (int j = 0; j < cc; j++) {
        float v = slots[j * NT + tid];
        int p = atomicAdd(&scnt, 1);
        if (p < SCAP) swin[p] = v;
    }

    int ovf = __syncthreads_or(c > NSLOT);        // per-thread slot overflow -> bad row
    int cb  = scnt;
    if (tid == 0)
        sbase = atomicAdd(&g_cnt[row],
                          (ovf || cb > SCAP) ? (unsigned)(WCAPG + 1) : (unsigned)cb);
    __syncthreads();
    if (!ovf && cb <= SCAP) {
        unsigned base = sbase;
        for (int i = tid; i < cb; i += NT) {
            unsigned p = base + (unsigned)i;
            if (p < WCAPG) g_win[(size_t)row * WCAPG + p] = swin[i];
        }
    }
}

// =================== K1b: per-row select + sort + MLP ===================
extern __shared__ float smk1b[];

__global__ void __launch_bounds__(NT)
k1b_sortmlp(const float* __restrict__ inp,
            const float* __restrict__ W1, const float* __restrict__ b1,
            const float* __restrict__ W2, const float* __restrict__ b2,
            const float* __restrict__ W3, const float* __restrict__ b3)
{
    float* win = smk1b;               // [WCAPG]
    float* buf = smk1b + WCAPG;       // [FCAP]
    __shared__ float redf[8];
    __shared__ int   redi[8];
    __shared__ int   sCnt;
    __shared__ float sh1[5];

    const int tid  = threadIdx.x;
    const int lane = tid & 31;
    const int wid  = tid >> 5;
    const int row  = blockIdx.x;
    const float* x = inp + (size_t)row * VV;

    const unsigned cntRaw = g_cnt[row];
    float tSel = THR0;
    int cnt = (int)min(cntRaw, (unsigned)WCAPG);

    for (int i = tid; i < cnt; i += NT) win[i] = g_win[(size_t)row * WCAPG + i];
    if (tid == 0) sCnt = 0;
    __syncthreads();

    const int bad = (cntRaw > (unsigned)WCAPG) || (cnt < TOPK);
    float M;

    if (bad) {
        // ---- rare exact fallback: exact max + global bisection + gather ----
        float mx = -INFINITY;
        #pragma unroll 8
        for (int i = tid; i < VV; i += NT) mx = fmaxf(mx, __ldg(x + i));
        M = blockMaxF(mx, redf, tid);
        float gap = 8.0f, lo = M - gap, hi = M;
        int c = cgtGlobal(x, lo, tid, redi);
        for (int e = 0; e < 12 && c < TOPK; e++) {
            gap *= 4.0f; lo = M - gap;
            c = cgtGlobal(x, lo, tid, redi);
        }
        float ts = hi; int found = 0;
        if (c >= TOPK && c <= FCAP) { ts = lo; found = 1; }
        for (int it = 0; it < 50 && !found; it++) {
            float mid = 0.5f * (lo + hi);
            if (mid <= lo || mid >= hi) break;        // tie plateau -> hi
            c = cgtGlobal(x, mid, tid, redi);
            if (c >= TOPK && c <= FCAP) { ts = mid; found = 1; }
            else if (c > FCAP) lo = mid; else hi = mid;
        }
        tSel = ts;
        #pragma unroll 4
        for (int i = tid; i < VV; i += NT) {
            float v = __ldg(x + i);
            if (v > tSel) { int p = atomicAdd(&sCnt, 1); if (p < FCAP) buf[p] = v; }
        }
        __syncthreads();
    } else {
        // exact row max = max of winners (cnt >= TOPK means max > THR0, so gathered)
        float mx = -INFINITY;
        for (int i = tid; i < cnt; i += NT) mx = fmaxf(mx, win[i]);
        M = blockMaxF(mx, redf, tid);
        if (cnt > FCAP) {
            float lo = tSel, hi = M;
            int found = 0;
            float ts = tSel;
            for (int it = 0; it < 40 && !found; it++) {
                float mid = 0.5f * (lo + hi);
                if (mid <= lo || mid >= hi) { ts = hi; break; }   // tie plateau
                int c = 0;
                for (int i = tid; i < cnt; i += NT) c += (win[i] > mid);
                c = blockSumI(c, redi, tid);
                if (c >= TOPK && c <= FCAP) { ts = mid; found = 1; }
                else if (c > FCAP) lo = mid; else hi = mid;
            }
            if (!found && ts == tSel) ts = hi;
            tSel = ts;
        }
        for (int i = tid; i < cnt; i += NT) {
            float v = win[i];
            if (v > tSel) { int p = atomicAdd(&sCnt, 1); if (p < FCAP) buf[p] = v; }
        }
        __syncthreads();
    }

    int bc = min(sCnt, FCAP);
    if (tid >= bc) buf[tid] = -INFINITY;          // pad (NT == FCAP)
    __syncthreads();

    // ---- bitonic sort 256 descending ----
    #pragma unroll 1
    for (int k = 2; k <= FCAP; k <<= 1) {
        #pragma unroll 1
        for (int j = k >> 1; j > 0; j >>= 1) {
            int i = tid, ixj = i ^ j;
            if (ixj > i) {
                float va = buf[i], vb = buf[ixj];
                bool desc = ((i & k) == 0);
                if (desc ? (va < vb) : (va > vb)) { buf[i] = vb; buf[ixj] = va; }
            }
            __syncthreads();
        }
    }
    // tie-plateau fill: missing top-k entries equal tSel by construction
    if (tid < TOPK && tid >= bc) buf[tid] = tSel;
    __syncthreads();

    // ---- tiny MLP -> temperature -> (a, b) ----
    if (wid < 5) {
        float acc = 0.0f;
        #pragma unroll
        for (int i = lane; i < TOPK; i += 32)
            acc = fmaf(__ldg(W1 + wid * TOPK + i), buf[i], acc);
        #pragma unroll
        for (int k = 16; k; k >>= 1) acc += __shfl_xor_sync(~0u, acc, k);
        if (lane == 0) sh1[wid] = fmaxf(acc + __ldg(b1 + wid), 0.0f);
    }
    __syncthreads();
    if (tid == 0) {
        float h2[5];
        #pragma unroll
        for (int j = 0; j < 5; ++j) {
            float a2 = __ldg(b2 + j);
            #pragma unroll
            for (int i = 0; i < 5; ++i) a2 = fmaf(__ldg(W2 + j * 5 + i), sh1[i], a2);
            h2[j] = fmaxf(a2, 0.0f);
        }
        float t0 = __ldg(b3);
        #pragma unroll
        for (int i = 0; i < 5; ++i) t0 = fmaf(__ldg(W3 + i), h2[i], t0);
        t0 = fabsf(t0);
        float sp   = (t0 > 20.0f) ? t0 : log1pf(expf(t0));
        float temp = fmaxf(sp, 1e-5f);
        float a    = 1.44269504088896340736f / temp;
        g_a[row] = a;
        g_b[row] = -M * a;
        g_cnt[row] = 0u;          // reset for next graph replay (ordered by stream)
    }
}

// =================== K2: pure segmented sum of exp ===================
__global__ void __launch_bounds__(NT)
k2_sumexp(const float* __restrict__ inp)
{
    const int row = blockIdx.x >> 2;
    const int seg = blockIdx.x & 3;
    const int tid = threadIdx.x;
    const float* x = inp + (size_t)row * VV;
    const float a = __ldg(&g_a[row]);
    const float b = __ldg(&g_b[row]);
    const int start = seg * SEGLEN;
    const int end   = min(VV, start + SEGLEN);

    float s = 0.0f;
    int i = start + tid;
    for (; i + 7 * NT < end; i += 8 * NT) {
        float v[8];
        #pragma unroll
        for (int j = 0; j < 8; j++) v[j] = __ldg(x + i + j * NT);
        #pragma unroll
        for (int j = 0; j < 8; j++) s += exp2_fast(fmaf(v[j], a, b));
    }
    for (; i < end; i += NT) s += exp2_fast(fmaf(__ldg(x + i), a, b));

    __shared__ float red[8];
    int lane = tid & 31, w = tid >> 5;
    #pragma unroll
    for (int k = 16; k; k >>= 1) s += __shfl_xor_sync(~0u, s, k);
    if (lane == 0) red[w] = s;
    __syncthreads();
    if (tid == 0) {
        float tot = 0.0f;
        #pragma unroll
        for (int k = 0; k < NT / 32; k++) tot += red[k];
        g_part[row * SEG + seg] = tot;
    }
}

__global__ void k3_final(const float* __restrict__ inp,
                         const int* __restrict__ tokens,
                         float* __restrict__ out, int nrows)
{
    int r = blockIdx.x * blockDim.x + threadIdx.x;
    if (r >= nrows) return;
    float s = g_part[r * SEG + 0] + g_part[r * SEG + 1]
            + g_part[r * SEG + 2] + g_part[r * SEG + 3];
    int tok = tokens[r];
    tok = (tok < 0) ? 0 : ((tok >= VV) ? VV - 1 : tok);
    float xt = __ldg(inp + (size_t)r * VV + tok);
    out[r] = exp2_fast(fmaf(xt, g_a[r], g_b[r])) / s;
}

extern "C" void kernel_launch(void* const* d_in, const int* in_sizes, int n_in,
                              void* d_out, int out_size)
{
    const float* inp    = (const float*)d_in[0];
    const int*   tokens = (const int*)d_in[1];
    const float* W1     = (const float*)d_in[2];
    const float* b1     = (const float*)d_in[3];
    const float* W2     = (const float*)d_in[4];
    const float* b2     = (const float*)d_in[5];
    const float* W3     = (const float*)d_in[6];
    const float* b3     = (const float*)d_in[7];
    float*       o      = (float*)d_out;

    int N = in_sizes[1];
    if (N > MAXN) N = MAXN;

    size_t smb = (size_t)(WCAPG + FCAP) * sizeof(float);   // 9 KB
    cudaFuncSetAttribute(k1b_sortmlp, cudaFuncAttributeMaxDynamicSharedMemorySize, (int)smb);

    k1_gather  <<<N * SEG, NT>>>(inp);
    k1b_sortmlp<<<N, NT, smb>>>(inp, W1, b1, W2, b2, W3, b3);
    k2_sumexp  <<<N * SEG, NT>>>(inp);
    k3_final   <<<(N + 255) / 256, 256>>>(inp, tokens, o, N);
}